// round 16
// baseline (speedup 1.0000x reference)
#include <cuda_runtime.h>
#include <cuda_fp16.h>
#include <math.h>
#include <stdint.h>

// ===========================================================================
// Live math (softmax over size-1 axis == 1 kills q/Wq/bq/rpb/k-half of Wkv).
// R16 ALGEBRAIC FUSION: v only feeds y, both affine =>
//   y = h @ (Wv@Wp) + (bv@Wp + bp)  -- Wp GEMM stage eliminated entirely.
//   z = y + gelu(LN(y;g2,b2)@W1+bm1)@W2 + bm2
// mma.sync m16n8k16 fp16 (fp32 accum), ldmatrix, persistent CTAs,
// 64 tokens/tile, 8 warps, 2 CTAs/SM.
// ===========================================================================

#define CC    384
#define DD    128
#define HIDN  512
#define MT    64
#define NTHR  256
#define EPSV  1e-5f
#define PGRID 304    // persistent CTAs (2 per SM, 152 SMs)

#define WSTR  136    // K=128 tile stride (halves); row step 272B -> ldsm-clean
#define VSTR  136

// smem byte offsets
#define OFF_BB   0          // 2 x (128x136) fp16 = 69632
#define OFF_VB   69632      // lny : 64 x 136 fp16 = 17408
#define OFF_GB   87040      // gelu / stage-2 A chunk : 64 x 136 fp16 = 17408
#define OFF_PSUM 104448     // 256 fp32
#define OFF_PSQ  105472     // 256 fp32
#define OFF_MEAN 106496     // 64 fp32
#define OFF_RSTD 106752     // 64 fp32
#define OFF_CTR  107008
#define OFF_G1S  107136     // 384 fp32 staged gamma1
#define OFF_B1S  108672     // 384 fp32 staged beta1
#define SMEM_BYTES 110208

// Fused / pre-transposed fp16 weights, [n][k] row-major (mma row.col B op)
__device__ __half g_WvpT[DD * CC];   // (Wv@Wp)^T
__device__ float  g_bvp[DD];         // bv@Wp + bp
__device__ __half g_W1T[HIDN * DD];
__device__ __half g_W2T[DD * HIDN];
__device__ int    g_ctr;

__device__ __forceinline__ uint32_t smem_u32(const void* p) {
    uint32_t a;
    asm("{ .reg .u64 t; cvta.to.shared.u64 t, %1; cvt.u32.u64 %0, t; }"
        : "=r"(a) : "l"(p));
    return a;
}
__device__ __forceinline__ void cp16(uint32_t dst, const void* src) {
    asm volatile("cp.async.cg.shared.global [%0], [%1], 16;"
                 :: "r"(dst), "l"(src));
}
__device__ __forceinline__ void cp_commit() {
    asm volatile("cp.async.commit_group;" ::: "memory");
}
template<int N> __device__ __forceinline__ void cp_wait() {
    asm volatile("cp.async.wait_group %0;" :: "n"(N) : "memory");
}
__device__ __forceinline__ void ldsm4(uint32_t r[4], uint32_t addr) {
    asm volatile("ldmatrix.sync.aligned.m8n8.x4.shared.b16 {%0,%1,%2,%3}, [%4];"
                 : "=r"(r[0]), "=r"(r[1]), "=r"(r[2]), "=r"(r[3]) : "r"(addr));
}
__device__ __forceinline__ void mma16(float c[4],
    uint32_t a0, uint32_t a1, uint32_t a2, uint32_t a3,
    uint32_t b0, uint32_t b1) {
    asm volatile(
        "mma.sync.aligned.m16n8k16.row.col.f32.f16.f16.f32 "
        "{%0,%1,%2,%3}, {%4,%5,%6,%7}, {%8,%9}, {%0,%1,%2,%3};"
        : "+f"(c[0]), "+f"(c[1]), "+f"(c[2]), "+f"(c[3])
        : "r"(a0), "r"(a1), "r"(a2), "r"(a3), "r"(b0), "r"(b1));
}

// Tanh-form gelu via sigmoid (short dep chain; dev < 2e-5 for |v|<1.5)
__device__ __forceinline__ float gelu_f(float v) {
    float v2 = v * v;
    float a  = fmaf(-0.0713548162726f, v2, -1.5957691216057f);
    float e  = __expf(v * a);
    return __fdividef(v, 1.f + e);
}

// ----- MMA body -----------------------------------------------------------
#define MMA_KSTEP(acc, aA0, aA1, aB0, aB1, koff) { \
    uint32_t a0[4], a1[4], b0[4], b1[4]; \
    ldsm4(a0, (aA0) + (koff)); ldsm4(a1, (aA1) + (koff)); \
    ldsm4(b0, (aB0) + (koff)); ldsm4(b1, (aB1) + (koff)); \
    mma16(acc[0][0], a0[0],a0[1],a0[2],a0[3], b0[0], b0[2]); \
    mma16(acc[0][1], a0[0],a0[1],a0[2],a0[3], b0[1], b0[3]); \
    mma16(acc[0][2], a0[0],a0[1],a0[2],a0[3], b1[0], b1[2]); \
    mma16(acc[0][3], a0[0],a0[1],a0[2],a0[3], b1[1], b1[3]); \
    mma16(acc[1][0], a1[0],a1[1],a1[2],a1[3], b0[0], b0[2]); \
    mma16(acc[1][1], a1[0],a1[1],a1[2],a1[3], b0[1], b0[3]); \
    mma16(acc[1][2], a1[0],a1[1],a1[2],a1[3], b1[0], b1[2]); \
    mma16(acc[1][3], a1[0],a1[1],a1[2],a1[3], b1[1], b1[3]); \
}

// K=128 GEMM: A stride VSTR, B stride WSTR
__device__ __forceinline__ void mma_gemm128(
    const __half* As, const __half* Bs,
    float acc[2][4][4], int wm, int wn, int lane)
{
    const int lrow = lane & 15;
    const int lcol = (lane >> 4) << 3;
    uint32_t aA0 = smem_u32(As + (wm * 32 +      lrow) * VSTR + lcol);
    uint32_t aA1 = smem_u32(As + (wm * 32 + 16 + lrow) * VSTR + lcol);
    uint32_t aB0 = smem_u32(Bs + (wn * 32 +      lrow) * WSTR + lcol);
    uint32_t aB1 = smem_u32(Bs + (wn * 32 + 16 + lrow) * WSTR + lcol);
    #pragma unroll
    for (int k0 = 0; k0 < 128; k0 += 16)
        MMA_KSTEP(acc, aA0, aA1, aB0, aB1, k0 * 2);
}

// ----- async B loader: 128 rows x 128 halves of Wg[n][ldw] ----------------
__device__ __forceinline__ void issueB128(__half* Bdst, const __half* __restrict__ Wg,
                                          int ldw, int tid)
{
    #pragma unroll
    for (int i = 0; i < 8; i++) {
        int idx = tid + NTHR * i;
        int row = idx >> 4;
        int g8  = (idx & 15) << 3;
        cp16(smem_u32(Bdst + row * WSTR + g8), Wg + row * ldw + g8);
    }
}

#define ZERO_ACC(A) { _Pragma("unroll") for (int _m=0;_m<2;_m++) \
    _Pragma("unroll") for (int _n=0;_n<4;_n++) \
    _Pragma("unroll") for (int _q=0;_q<4;_q++) (A)[_m][_n][_q] = 0.f; }

// -------- prep 1: W1/W2 tiled transposes (fp32->fp16) + counter reset -----
__global__ void prep_all(const float* __restrict__ W1,
                         const float* __restrict__ W2)
{
    if (blockIdx.x == 0 && threadIdx.x == 0 && threadIdx.y == 0)
        g_ctr = 0;

    const float* src; __half* dst;
    int K, lds, kb, nb;
    int b = blockIdx.x;
    if (b < 64) { src = W1; dst = g_W1T; K = DD;   lds = HIDN;
                  kb = b % 4;  nb = b / 4; }
    else        { int i = b - 64; src = W2; dst = g_W2T; K = HIDN; lds = DD;
                  kb = i % 16; nb = i / 16; }

    __shared__ float tile[32][33];
    int k0 = kb * 32, n0 = nb * 32;
    int tx = threadIdx.x, ty = threadIdx.y;
    #pragma unroll
    for (int j = 0; j < 4; j++)
        tile[ty + 8 * j][tx] = src[(k0 + ty + 8 * j) * lds + n0 + tx];
    __syncthreads();
    #pragma unroll
    for (int j = 0; j < 4; j++)
        dst[(n0 + ty + 8 * j) * K + k0 + tx] =
            __float2half_rn(tile[tx][ty + 8 * j]);
}

// -------- prep 2: fused weight  WvpT = (Wv@Wp)^T,  bvp = bv@Wp + bp -------
__global__ void prep_fuse(const float* __restrict__ Wkv,
                          const float* __restrict__ Wp,
                          const float* __restrict__ bkv,
                          const float* __restrict__ bp)
{
    int b = blockIdx.x;
    if (b < 192) {
        int idx = b * 256 + threadIdx.x;     // 49152 = 384*128
        int n = idx & 127, k = idx >> 7;
        float s = 0.f;
        #pragma unroll 4
        for (int j = 0; j < 128; j++)
            s += Wkv[k * 256 + 128 + j] * Wp[j * DD + n];
        g_WvpT[n * CC + k] = __float2half_rn(s);
    } else if (threadIdx.x < DD) {
        int n = threadIdx.x;
        float s = bp[n];
        for (int j = 0; j < 128; j++)
            s += bkv[128 + j] * Wp[j * DD + n];
        g_bvp[n] = s;
    }
}

// ------------------------------ main kernel -------------------------------
extern __shared__ char smem_raw[];

__global__ void __launch_bounds__(NTHR, 2) fused_mma(
    const float* __restrict__ x,
    const float* __restrict__ g1, const float* __restrict__ b1,
    const float* __restrict__ g2, const float* __restrict__ b2,
    const float* __restrict__ bm1, const float* __restrict__ bm2,
    float* __restrict__ out, int ntiles)
{
    __half* BwA = (__half*)(smem_raw + OFF_BB);
    __half* BwB = BwA + 128 * WSTR;
    __half* Vb  = (__half*)(smem_raw + OFF_VB);
    __half* Gb  = (__half*)(smem_raw + OFF_GB);
    __half* Ab  = (__half*)(smem_raw + OFF_GB);  // stage-2 A chunk alias
    float* psum  = (float*)(smem_raw + OFF_PSUM);
    float* psq   = (float*)(smem_raw + OFF_PSQ);
    float* smean = (float*)(smem_raw + OFF_MEAN);
    float* srstd = (float*)(smem_raw + OFF_RSTD);
    float* g1s   = (float*)(smem_raw + OFF_G1S);
    float* b1s   = (float*)(smem_raw + OFF_B1S);
    volatile int* stile = (volatile int*)(smem_raw + OFF_CTR);

    const int tid  = threadIdx.x;
    const int lane = tid & 31;
    const int warp = tid >> 5;
    const int wm   = warp >> 2;
    const int wn   = warp & 3;
    const int gid  = lane >> 2;
    const int tig  = lane & 3;

    // Stage g1/b1 once per CTA (visibility via loop-top barrier)
    #pragma unroll
    for (int i = tid; i < CC; i += NTHR) {
        g1s[i] = g1[i];
        b1s[i] = b1[i];
    }

    for (;;) {
        if (tid == 0) *stile = atomicAdd(&g_ctr, 1);
        __syncthreads();             // broadcast; smem free; staging visible
        int t = *stile;
        if (t >= ntiles) break;
        const long tile0 = (long)t * MT;

        // Prefetch Wvp chunk0 -> BwA (hides under LN stats)
        issueB128(BwA, g_WvpT, CC, tid); cp_commit();

        // ---- LN(x) stats + fused chunk-0 A-fill (vectorized) ----
        #pragma unroll 1
        for (int i = 0; i < 8; i++) {
            int row = warp * 8 + i;
            const float4* xr4 = (const float4*)(x + (tile0 + row) * CC);
            float4 a0 = xr4[lane];
            float4 a1 = xr4[lane + 32];
            float4 a2 = xr4[lane + 64];
            float s  = (a0.x + a0.y) + (a0.z + a0.w)
                     + (a1.x + a1.y) + (a1.z + a1.w)
                     + (a2.x + a2.y) + (a2.z + a2.w);
            float ss = (a0.x*a0.x + a0.y*a0.y) + (a0.z*a0.z + a0.w*a0.w)
                     + (a1.x*a1.x + a1.y*a1.y) + (a1.z*a1.z + a1.w*a1.w)
                     + (a2.x*a2.x + a2.y*a2.y) + (a2.z*a2.z + a2.w*a2.w);
            #pragma unroll
            for (int o = 16; o > 0; o >>= 1) {
                s  += __shfl_xor_sync(0xffffffffu, s,  o);
                ss += __shfl_xor_sync(0xffffffffu, ss, o);
            }
            float m  = s * (1.f / 384.f);
            float v  = ss * (1.f / 384.f) - m * m;
            float rs = rsqrtf(v + EPSV);
            if (lane == 0) { smean[row] = m; srstd[row] = rs; }
            int k = lane * 4;
            float4 gg = *(const float4*)(g1s + k);
            float4 bb = *(const float4*)(b1s + k);
            __half2 h0 = __floats2half2_rn(fmaf((a0.x - m) * rs, gg.x, bb.x),
                                           fmaf((a0.y - m) * rs, gg.y, bb.y));
            __half2 h1 = __floats2half2_rn(fmaf((a0.z - m) * rs, gg.z, bb.z),
                                           fmaf((a0.w - m) * rs, gg.w, bb.w));
            uint2 pk = make_uint2(*(uint32_t*)&h0, *(uint32_t*)&h1);
            *(uint2*)(Ab + row * VSTR + k) = pk;
        }
        __syncthreads();

        // ----- y = LN(x) @ WvpT : 3 x K=128 chunks, BwA/BwB ping-pong -----
        float yacc[2][4][4];
        ZERO_ACC(yacc);
        #pragma unroll 1
        for (int c = 0; c < 3; c++) {
            __half* Bcur = (c & 1) ? BwB : BwA;
            if (c == 0)      { issueB128(BwB, g_WvpT + 128, CC, tid); cp_commit(); }
            else if (c == 1) { issueB128(BwA, g_WvpT + 256, CC, tid); cp_commit(); }
            else             { issueB128(BwB, g_W1T, DD, tid);        cp_commit(); }

            if (c > 0) {
                int kc = c * 128;
                #pragma unroll
                for (int i = 0; i < 8; i++) {
                    int idx = tid + NTHR * i;        // 64 rows x 32 quads
                    int row = idx >> 5, q = (idx & 31) * 4;
                    int k = kc + q;
                    float4 xx = *(const float4*)(x + (tile0 + row) * CC + k);
                    float4 gg = *(const float4*)(g1s + k);
                    float4 bb = *(const float4*)(b1s + k);
                    float m = smean[row], rs = srstd[row];
                    __half2 h0 = __floats2half2_rn(fmaf((xx.x - m) * rs, gg.x, bb.x),
                                                   fmaf((xx.y - m) * rs, gg.y, bb.y));
                    __half2 h1 = __floats2half2_rn(fmaf((xx.z - m) * rs, gg.z, bb.z),
                                                   fmaf((xx.w - m) * rs, gg.w, bb.w));
                    uint2 pk = make_uint2(*(uint32_t*)&h0, *(uint32_t*)&h1);
                    *(uint2*)(Ab + row * VSTR + q) = pk;
                }
            }
            cp_wait<1>();
            __syncthreads();         // chunk-c B ready; Ab published
            mma_gemm128(Ab, Bcur, yacc, wm, wn, lane);
            __syncthreads();         // all past gemm: next refills are safe
        }
        // After stage 2: W1(0) pending into BwB.

        // ------ y epilogue: +bvp, y -> global, LN(y) stats via shfl -------
        #pragma unroll
        for (int mi = 0; mi < 2; mi++)
            #pragma unroll
            for (int ni = 0; ni < 4; ni++) {
                int r0 = wm * 32 + mi * 16 + gid;
                int cb = wn * 32 + ni * 8 + tig * 2;
                float bb0 = g_bvp[cb], bb1 = g_bvp[cb + 1];
                yacc[mi][ni][0] += bb0;  yacc[mi][ni][1] += bb1;
                yacc[mi][ni][2] += bb0;  yacc[mi][ni][3] += bb1;
                float2 z0 = make_float2(yacc[mi][ni][0], yacc[mi][ni][1]);
                float2 z1 = make_float2(yacc[mi][ni][2], yacc[mi][ni][3]);
                *(float2*)(out + (tile0 + r0) * DD + cb)     = z0;
                *(float2*)(out + (tile0 + r0 + 8) * DD + cb) = z1;
            }
        #pragma unroll
        for (int mi = 0; mi < 2; mi++) {
            float s0 = 0.f, q0 = 0.f, s1 = 0.f, q1 = 0.f;
            #pragma unroll
            for (int ni = 0; ni < 4; ni++) {
                float a = yacc[mi][ni][0], b = yacc[mi][ni][1];
                float c = yacc[mi][ni][2], d = yacc[mi][ni][3];
                s0 += a + b;  q0 += a * a + b * b;
                s1 += c + d;  q1 += c * c + d * d;
            }
            #pragma unroll
            for (int o = 1; o <= 2; o <<= 1) {
                s0 += __shfl_xor_sync(0xffffffffu, s0, o);
                q0 += __shfl_xor_sync(0xffffffffu, q0, o);
                s1 += __shfl_xor_sync(0xffffffffu, s1, o);
                q1 += __shfl_xor_sync(0xffffffffu, q1, o);
            }
            if (tig == 0) {
                int row = wm * 32 + mi * 16 + gid;
                psum[wn * 64 + row]     = s0;  psq[wn * 64 + row]     = q0;
                psum[wn * 64 + row + 8] = s1;  psq[wn * 64 + row + 8] = q1;
            }
        }
        __syncthreads();             // psum ready

        // lny -> Vb (fp16) from registers
        #pragma unroll
        for (int mi = 0; mi < 2; mi++) {
            int rA = wm * 32 + mi * 16 + gid;
            int rB = rA + 8;
            float mA = (psum[rA] + psum[64 + rA] + psum[128 + rA] + psum[192 + rA]) * (1.f / 128.f);
            float vA = (psq [rA] + psq [64 + rA] + psq [128 + rA] + psq [192 + rA]) * (1.f / 128.f) - mA * mA;
            float mB = (psum[rB] + psum[64 + rB] + psum[128 + rB] + psum[192 + rB]) * (1.f / 128.f);
            float vB = (psq [rB] + psq [64 + rB] + psq [128 + rB] + psq [192 + rB]) * (1.f / 128.f) - mB * mB;
            float rsA = rsqrtf(vA + EPSV), rsB = rsqrtf(vB + EPSV);
            #pragma unroll
            for (int ni = 0; ni < 4; ni++) {
                int cb = wn * 32 + ni * 8 + tig * 2;
                float gg0 = g2[cb], gg1 = g2[cb + 1];
                float bb0 = b2[cb], bb1 = b2[cb + 1];
                *(__half2*)(Vb + rA * VSTR + cb) = __floats2half2_rn(
                    fmaf((yacc[mi][ni][0] - mA) * rsA, gg0, bb0),
                    fmaf((yacc[mi][ni][1] - mA) * rsA, gg1, bb1));
                *(__half2*)(Vb + rB * VSTR + cb) = __floats2half2_rn(
                    fmaf((yacc[mi][ni][2] - mB) * rsB, gg0, bb0),
                    fmaf((yacc[mi][ni][3] - mB) * rsB, gg1, bb1));
            }
        }
        // yacc dead (y lives in global)

        // ---- MLP: 4 hidden tiles; W1 in BwB, W2 in BwA; 2 barriers/iter ---
        float uacc[2][4][4];
        ZERO_ACC(uacc);
        #pragma unroll 1
        for (int cc = 0; cc < 4; cc++) {
            cp_wait<0>();            // W1(cc) in BwB done
            __syncthreads();         // lny published; prev uacc gemm done (BwA free)
            issueB128(BwA, g_W2T + cc * 128, HIDN, tid); cp_commit();
            float tacc[2][4][4];
            ZERO_ACC(tacc);
            mma_gemm128(Vb, BwB, tacc, wm, wn, lane);

            // gelu -> Gb (per-warp-owned regions; no sync needed before)
            #pragma unroll
            for (int mi = 0; mi < 2; mi++)
                #pragma unroll
                for (int ni = 0; ni < 4; ni++) {
                    int r0 = wm * 32 + mi * 16 + gid;
                    int cb = wn * 32 + ni * 8 + tig * 2;
                    float bb0 = bm1[cc * 128 + cb], bb1 = bm1[cc * 128 + cb + 1];
                    *(__half2*)(Gb + r0 * VSTR + cb) = __floats2half2_rn(
                        gelu_f(tacc[mi][ni][0] + bb0),
                        gelu_f(tacc[mi][ni][1] + bb1));
                    *(__half2*)(Gb + (r0 + 8) * VSTR + cb) = __floats2half2_rn(
                        gelu_f(tacc[mi][ni][2] + bb0),
                        gelu_f(tacc[mi][ni][3] + bb1));
                }
            cp_wait<0>();            // W2(cc) in BwA done
            __syncthreads();         // Gb published; all past tacc (BwB free)
            if (cc < 3) {
                issueB128(BwB, g_W1T + (cc + 1) * 128 * DD, DD, tid);
                cp_commit();
            }
            mma_gemm128(Gb, BwA, uacc, wm, wn, lane);
        }

        // -------- z = y(reload, own addresses) + u + bm2 -> out -----------
        #pragma unroll
        for (int mi = 0; mi < 2; mi++)
            #pragma unroll
            for (int ni = 0; ni < 4; ni++) {
                int r0 = wm * 32 + mi * 16 + gid;
                int cb = wn * 32 + ni * 8 + tig * 2;
                float bb0 = bm2[cb], bb1 = bm2[cb + 1];
                float2 ya = *(float2*)(out + (tile0 + r0) * DD + cb);
                float2 yb = *(float2*)(out + (tile0 + r0 + 8) * DD + cb);
                float2 z0, z1;
                z0.x = ya.x + uacc[mi][ni][0] + bb0;
                z0.y = ya.y + uacc[mi][ni][1] + bb1;
                z1.x = yb.x + uacc[mi][ni][2] + bb0;
                z1.y = yb.y + uacc[mi][ni][3] + bb1;
                *(float2*)(out + (tile0 + r0) * DD + cb)     = z0;
                *(float2*)(out + (tile0 + r0 + 8) * DD + cb) = z1;
            }
    }
}

// ------------------------------ launcher ----------------------------------
extern "C" void kernel_launch(void* const* d_in, const int* in_sizes, int n_in,
                              void* d_out, int out_size)
{
    const float* x   = (const float*)d_in[0];
    const float* g1  = (const float*)d_in[1];
    const float* b1  = (const float*)d_in[2];
    // d_in[3]=Wq, d_in[4]=bq, d_in[7]=rpb : dead
    const float* Wkv = (const float*)d_in[5];
    const float* bkv = (const float*)d_in[6];
    const float* Wp  = (const float*)d_in[8];
    const float* bp  = (const float*)d_in[9];
    const float* g2  = (const float*)d_in[10];
    const float* b2  = (const float*)d_in[11];
    const float* W1  = (const float*)d_in[12];
    const float* bm1 = (const float*)d_in[13];
    const float* W2  = (const float*)d_in[14];
    const float* bm2 = (const float*)d_in[15];
    float* out = (float*)d_out;

    cudaFuncSetAttribute(fused_mma,
                         cudaFuncAttributeMaxDynamicSharedMemorySize,
                         SMEM_BYTES);

    prep_all<<<128, dim3(32, 8)>>>(W1, W2);            // also resets g_ctr
    prep_fuse<<<193, 256>>>(Wkv, Wp, bkv, bp);         // WvpT, bvp

    const int tokens = in_sizes[0] / CC;   // 65536
    const int ntiles = tokens / MT;        // 1024
    fused_mma<<<PGRID, NTHR, SMEM_BYTES>>>(
        x, g1, b1, g2, b2, bm1, bm2, out, ntiles);
}

// round 17
// speedup vs baseline: 1.0427x; 1.0427x over previous
#include <cuda_runtime.h>
#include <cuda_fp16.h>
#include <math.h>
#include <stdint.h>

// ===========================================================================
// Live math (softmax over size-1 axis == 1 kills q/Wq/bq/rpb/k-half of Wkv).
// Algebraic fusion: y = h @ (Wv@Wp) + (bv@Wp + bp); Wp GEMM eliminated.
//   z = y + gelu(LN(y;g2,b2)@W1+bm1)@W2 + bm2
// mma.sync m16n8k16 fp16 (fp32 accum), ldmatrix, persistent CTAs,
// 64 tokens/tile, 8 warps, 2 CTAs/SM.
// R17: single merged prep launch; static persistent tiling (no atomic);
// L2 prefetch of next tile's x issued after stage 2.
// ===========================================================================

#define CC    384
#define DD    128
#define HIDN  512
#define MT    64
#define NTHR  256
#define EPSV  1e-5f
#define PGRID 304    // persistent CTAs (2 per SM, 152 SMs)

#define WSTR  136
#define VSTR  136

// smem byte offsets
#define OFF_BB   0          // 2 x (128x136) fp16 = 69632
#define OFF_VB   69632      // lny : 64 x 136 fp16 = 17408
#define OFF_GB   87040      // gelu / stage-2 A chunk : 64 x 136 fp16 = 17408
#define OFF_PSUM 104448     // 256 fp32
#define OFF_PSQ  105472     // 256 fp32
#define OFF_MEAN 106496     // 64 fp32
#define OFF_RSTD 106752     // 64 fp32
#define OFF_G1S  107008     // 384 fp32 staged gamma1
#define OFF_B1S  108544     // 384 fp32 staged beta1
#define SMEM_BYTES 110080

// Fused / pre-transposed fp16 weights, [n][k] row-major (mma row.col B op)
__device__ __half g_WvpT[DD * CC];   // (Wv@Wp)^T
__device__ float  g_bvp[DD];         // bv@Wp + bp
__device__ __half g_W1T[HIDN * DD];
__device__ __half g_W2T[DD * HIDN];

__device__ __forceinline__ uint32_t smem_u32(const void* p) {
    uint32_t a;
    asm("{ .reg .u64 t; cvta.to.shared.u64 t, %1; cvt.u32.u64 %0, t; }"
        : "=r"(a) : "l"(p));
    return a;
}
__device__ __forceinline__ void cp16(uint32_t dst, const void* src) {
    asm volatile("cp.async.cg.shared.global [%0], [%1], 16;"
                 :: "r"(dst), "l"(src));
}
__device__ __forceinline__ void cp_commit() {
    asm volatile("cp.async.commit_group;" ::: "memory");
}
template<int N> __device__ __forceinline__ void cp_wait() {
    asm volatile("cp.async.wait_group %0;" :: "n"(N) : "memory");
}
__device__ __forceinline__ void prefetchL2(const void* p) {
    asm volatile("prefetch.global.L2 [%0];" :: "l"(p));
}
__device__ __forceinline__ void ldsm4(uint32_t r[4], uint32_t addr) {
    asm volatile("ldmatrix.sync.aligned.m8n8.x4.shared.b16 {%0,%1,%2,%3}, [%4];"
                 : "=r"(r[0]), "=r"(r[1]), "=r"(r[2]), "=r"(r[3]) : "r"(addr));
}
__device__ __forceinline__ void mma16(float c[4],
    uint32_t a0, uint32_t a1, uint32_t a2, uint32_t a3,
    uint32_t b0, uint32_t b1) {
    asm volatile(
        "mma.sync.aligned.m16n8k16.row.col.f32.f16.f16.f32 "
        "{%0,%1,%2,%3}, {%4,%5,%6,%7}, {%8,%9}, {%0,%1,%2,%3};"
        : "+f"(c[0]), "+f"(c[1]), "+f"(c[2]), "+f"(c[3])
        : "r"(a0), "r"(a1), "r"(a2), "r"(a3), "r"(b0), "r"(b1));
}

// Tanh-form gelu via sigmoid (short dep chain; dev < 2e-5 for |v|<1.5)
__device__ __forceinline__ float gelu_f(float v) {
    float v2 = v * v;
    float a  = fmaf(-0.0713548162726f, v2, -1.5957691216057f);
    float e  = __expf(v * a);
    return __fdividef(v, 1.f + e);
}

// ----- MMA body -----------------------------------------------------------
#define MMA_KSTEP(acc, aA0, aA1, aB0, aB1, koff) { \
    uint32_t a0[4], a1[4], b0[4], b1[4]; \
    ldsm4(a0, (aA0) + (koff)); ldsm4(a1, (aA1) + (koff)); \
    ldsm4(b0, (aB0) + (koff)); ldsm4(b1, (aB1) + (koff)); \
    mma16(acc[0][0], a0[0],a0[1],a0[2],a0[3], b0[0], b0[2]); \
    mma16(acc[0][1], a0[0],a0[1],a0[2],a0[3], b0[1], b0[3]); \
    mma16(acc[0][2], a0[0],a0[1],a0[2],a0[3], b1[0], b1[2]); \
    mma16(acc[0][3], a0[0],a0[1],a0[2],a0[3], b1[1], b1[3]); \
    mma16(acc[1][0], a1[0],a1[1],a1[2],a1[3], b0[0], b0[2]); \
    mma16(acc[1][1], a1[0],a1[1],a1[2],a1[3], b0[1], b0[3]); \
    mma16(acc[1][2], a1[0],a1[1],a1[2],a1[3], b1[0], b1[2]); \
    mma16(acc[1][3], a1[0],a1[1],a1[2],a1[3], b1[1], b1[3]); \
}

__device__ __forceinline__ void mma_gemm128(
    const __half* As, const __half* Bs,
    float acc[2][4][4], int wm, int wn, int lane)
{
    const int lrow = lane & 15;
    const int lcol = (lane >> 4) << 3;
    uint32_t aA0 = smem_u32(As + (wm * 32 +      lrow) * VSTR + lcol);
    uint32_t aA1 = smem_u32(As + (wm * 32 + 16 + lrow) * VSTR + lcol);
    uint32_t aB0 = smem_u32(Bs + (wn * 32 +      lrow) * WSTR + lcol);
    uint32_t aB1 = smem_u32(Bs + (wn * 32 + 16 + lrow) * WSTR + lcol);
    #pragma unroll
    for (int k0 = 0; k0 < 128; k0 += 16)
        MMA_KSTEP(acc, aA0, aA1, aB0, aB1, k0 * 2);
}

__device__ __forceinline__ void issueB128(__half* Bdst, const __half* __restrict__ Wg,
                                          int ldw, int tid)
{
    #pragma unroll
    for (int i = 0; i < 8; i++) {
        int idx = tid + NTHR * i;
        int row = idx >> 4;
        int g8  = (idx & 15) << 3;
        cp16(smem_u32(Bdst + row * WSTR + g8), Wg + row * ldw + g8);
    }
}

#define ZERO_ACC(A) { _Pragma("unroll") for (int _m=0;_m<2;_m++) \
    _Pragma("unroll") for (int _n=0;_n<4;_n++) \
    _Pragma("unroll") for (int _q=0;_q<4;_q++) (A)[_m][_n][_q] = 0.f; }

// ------------- merged prep: ONE launch does everything --------------------
// blocks [0,64): W1 transpose; [64,128): W2 transpose;
// blocks [128,320): WvpT = (Wv@Wp)^T fp32-accum; block 320: bvp.
__global__ void prep_merged(const float* __restrict__ W1,
                            const float* __restrict__ W2,
                            const float* __restrict__ Wkv,
                            const float* __restrict__ Wp,
                            const float* __restrict__ bkv,
                            const float* __restrict__ bp)
{
    int b = blockIdx.x;
    int tx = threadIdx.x, ty = threadIdx.y;
    int tid = ty * 32 + tx;

    if (b < 128) {
        const float* src; __half* dst;
        int K, lds, kb, nb;
        if (b < 64) { src = W1; dst = g_W1T; K = DD;   lds = HIDN;
                      kb = b % 4;  nb = b / 4; }
        else        { int i = b - 64; src = W2; dst = g_W2T; K = HIDN; lds = DD;
                      kb = i % 16; nb = i / 16; }
        __shared__ float tile[32][33];
        int k0 = kb * 32, n0 = nb * 32;
        #pragma unroll
        for (int j = 0; j < 4; j++)
            tile[ty + 8 * j][tx] = src[(k0 + ty + 8 * j) * lds + n0 + tx];
        __syncthreads();
        #pragma unroll
        for (int j = 0; j < 4; j++)
            dst[(n0 + ty + 8 * j) * K + k0 + tx] =
                __float2half_rn(tile[tx][ty + 8 * j]);
    } else if (b < 320) {
        int idx = (b - 128) * 256 + tid;     // 49152 = 384*128
        int n = idx & 127, k = idx >> 7;
        const float* wk = Wkv + k * 256 + 128;
        float s = 0.f;
        #pragma unroll 8
        for (int j = 0; j < 128; j++)
            s = fmaf(wk[j], Wp[j * DD + n], s);
        g_WvpT[n * CC + k] = __float2half_rn(s);
    } else if (tid < DD) {
        int n = tid;
        float s = bp[n];
        for (int j = 0; j < 128; j++)
            s = fmaf(bkv[128 + j], Wp[j * DD + n], s);
        g_bvp[n] = s;
    }
}

// ------------------------------ main kernel -------------------------------
extern __shared__ char smem_raw[];

__global__ void __launch_bounds__(NTHR, 2) fused_mma(
    const float* __restrict__ x,
    const float* __restrict__ g1, const float* __restrict__ b1,
    const float* __restrict__ g2, const float* __restrict__ b2,
    const float* __restrict__ bm1, const float* __restrict__ bm2,
    float* __restrict__ out, int ntiles)
{
    __half* BwA = (__half*)(smem_raw + OFF_BB);
    __half* BwB = BwA + 128 * WSTR;
    __half* Vb  = (__half*)(smem_raw + OFF_VB);
    __half* Gb  = (__half*)(smem_raw + OFF_GB);
    __half* Ab  = (__half*)(smem_raw + OFF_GB);  // stage-2 A chunk alias
    float* psum  = (float*)(smem_raw + OFF_PSUM);
    float* psq   = (float*)(smem_raw + OFF_PSQ);
    float* smean = (float*)(smem_raw + OFF_MEAN);
    float* srstd = (float*)(smem_raw + OFF_RSTD);
    float* g1s   = (float*)(smem_raw + OFF_G1S);
    float* b1s   = (float*)(smem_raw + OFF_B1S);

    const int tid  = threadIdx.x;
    const int lane = tid & 31;
    const int warp = tid >> 5;
    const int wm   = warp >> 2;
    const int wn   = warp & 3;
    const int gid  = lane >> 2;
    const int tig  = lane & 3;

    // Stage g1/b1 once per CTA (visibility via loop-top barrier)
    #pragma unroll
    for (int i = tid; i < CC; i += NTHR) {
        g1s[i] = g1[i];
        b1s[i] = b1[i];
    }

    // Static persistent tiling: deterministic -> next tile prefetchable.
    #pragma unroll 1
    for (int t = blockIdx.x; t < ntiles; t += PGRID) {
        __syncthreads();             // smem free from prev tile; staging visible
        const long tile0 = (long)t * MT;

        // Prefetch Wvp chunk0 -> BwA (hides under LN stats)
        issueB128(BwA, g_WvpT, CC, tid); cp_commit();

        // ---- LN(x) stats + fused chunk-0 A-fill (vectorized) ----
        #pragma unroll 1
        for (int i = 0; i < 8; i++) {
            int row = warp * 8 + i;
            const float4* xr4 = (const float4*)(x + (tile0 + row) * CC);
            float4 a0 = xr4[lane];
            float4 a1 = xr4[lane + 32];
            float4 a2 = xr4[lane + 64];
            float s  = (a0.x + a0.y) + (a0.z + a0.w)
                     + (a1.x + a1.y) + (a1.z + a1.w)
                     + (a2.x + a2.y) + (a2.z + a2.w);
            float ss = (a0.x*a0.x + a0.y*a0.y) + (a0.z*a0.z + a0.w*a0.w)
                     + (a1.x*a1.x + a1.y*a1.y) + (a1.z*a1.z + a1.w*a1.w)
                     + (a2.x*a2.x + a2.y*a2.y) + (a2.z*a2.z + a2.w*a2.w);
            #pragma unroll
            for (int o = 16; o > 0; o >>= 1) {
                s  += __shfl_xor_sync(0xffffffffu, s,  o);
                ss += __shfl_xor_sync(0xffffffffu, ss, o);
            }
            float m  = s * (1.f / 384.f);
            float v  = ss * (1.f / 384.f) - m * m;
            float rs = rsqrtf(v + EPSV);
            if (lane == 0) { smean[row] = m; srstd[row] = rs; }
            int k = lane * 4;
            float4 gg = *(const float4*)(g1s + k);
            float4 bb = *(const float4*)(b1s + k);
            __half2 h0 = __floats2half2_rn(fmaf((a0.x - m) * rs, gg.x, bb.x),
                                           fmaf((a0.y - m) * rs, gg.y, bb.y));
            __half2 h1 = __floats2half2_rn(fmaf((a0.z - m) * rs, gg.z, bb.z),
                                           fmaf((a0.w - m) * rs, gg.w, bb.w));
            uint2 pk = make_uint2(*(uint32_t*)&h0, *(uint32_t*)&h1);
            *(uint2*)(Ab + row * VSTR + k) = pk;
        }
        __syncthreads();

        // ----- y = LN(x) @ WvpT : 3 x K=128 chunks, BwA/BwB ping-pong -----
        float yacc[2][4][4];
        ZERO_ACC(yacc);
        #pragma unroll 1
        for (int c = 0; c < 3; c++) {
            __half* Bcur = (c & 1) ? BwB : BwA;
            if (c == 0)      { issueB128(BwB, g_WvpT + 128, CC, tid); cp_commit(); }
            else if (c == 1) { issueB128(BwA, g_WvpT + 256, CC, tid); cp_commit(); }
            else             { issueB128(BwB, g_W1T, DD, tid);        cp_commit(); }

            if (c > 0) {
                int kc = c * 128;
                #pragma unroll
                for (int i = 0; i < 8; i++) {
                    int idx = tid + NTHR * i;        // 64 rows x 32 quads
                    int row = idx >> 5, q = (idx & 31) * 4;
                    int k = kc + q;
                    float4 xx = *(const float4*)(x + (tile0 + row) * CC + k);
                    float4 gg = *(const float4*)(g1s + k);
                    float4 bb = *(const float4*)(b1s + k);
                    float m = smean[row], rs = srstd[row];
                    __half2 h0 = __floats2half2_rn(fmaf((xx.x - m) * rs, gg.x, bb.x),
                                                   fmaf((xx.y - m) * rs, gg.y, bb.y));
                    __half2 h1 = __floats2half2_rn(fmaf((xx.z - m) * rs, gg.z, bb.z),
                                                   fmaf((xx.w - m) * rs, gg.w, bb.w));
                    uint2 pk = make_uint2(*(uint32_t*)&h0, *(uint32_t*)&h1);
                    *(uint2*)(Ab + row * VSTR + q) = pk;
                }
            }
            cp_wait<1>();
            __syncthreads();         // chunk-c B ready; Ab published
            mma_gemm128(Ab, Bcur, yacc, wm, wn, lane);
            __syncthreads();         // all past gemm: next refills are safe
        }
        // After stage 2: W1(0) pending into BwB.

        // Prefetch next tile's x into L2 (deterministic next tile).
        if (t + PGRID < ntiles) {
            const char* nx = (const char*)(x + (long)(t + PGRID) * MT * CC);
            #pragma unroll
            for (int i = 0; i < 3; i++)
                prefetchL2(nx + (tid + 256 * i) * 128);
        }

        // ------ y epilogue: +bvp, y -> global, LN(y) stats via shfl -------
        #pragma unroll
        for (int mi = 0; mi < 2; mi++)
            #pragma unroll
            for (int ni = 0; ni < 4; ni++) {
                int r0 = wm * 32 + mi * 16 + gid;
                int cb = wn * 32 + ni * 8 + tig * 2;
                float bb0 = g_bvp[cb], bb1 = g_bvp[cb + 1];
                yacc[mi][ni][0] += bb0;  yacc[mi][ni][1] += bb1;
                yacc[mi][ni][2] += bb0;  yacc[mi][ni][3] += bb1;
                float2 z0 = make_float2(yacc[mi][ni][0], yacc[mi][ni][1]);
                float2 z1 = make_float2(yacc[mi][ni][2], yacc[mi][ni][3]);
                *(float2*)(out + (tile0 + r0) * DD + cb)     = z0;
                *(float2*)(out + (tile0 + r0 + 8) * DD + cb) = z1;
            }
        #pragma unroll
        for (int mi = 0; mi < 2; mi++) {
            float s0 = 0.f, q0 = 0.f, s1 = 0.f, q1 = 0.f;
            #pragma unroll
            for (int ni = 0; ni < 4; ni++) {
                float a = yacc[mi][ni][0], b = yacc[mi][ni][1];
                float c = yacc[mi][ni][2], d = yacc[mi][ni][3];
                s0 += a + b;  q0 += a * a + b * b;
                s1 += c + d;  q1 += c * c + d * d;
            }
            #pragma unroll
            for (int o = 1; o <= 2; o <<= 1) {
                s0 += __shfl_xor_sync(0xffffffffu, s0, o);
                q0 += __shfl_xor_sync(0xffffffffu, q0, o);
                s1 += __shfl_xor_sync(0xffffffffu, s1, o);
                q1 += __shfl_xor_sync(0xffffffffu, q1, o);
            }
            if (tig == 0) {
                int row = wm * 32 + mi * 16 + gid;
                psum[wn * 64 + row]     = s0;  psq[wn * 64 + row]     = q0;
                psum[wn * 64 + row + 8] = s1;  psq[wn * 64 + row + 8] = q1;
            }
        }
        __syncthreads();             // psum ready

        // lny -> Vb (fp16) from registers
        #pragma unroll
        for (int mi = 0; mi < 2; mi++) {
            int rA = wm * 32 + mi * 16 + gid;
            int rB = rA + 8;
            float mA = (psum[rA] + psum[64 + rA] + psum[128 + rA] + psum[192 + rA]) * (1.f / 128.f);
            float vA = (psq [rA] + psq [64 + rA] + psq [128 + rA] + psq [192 + rA]) * (1.f / 128.f) - mA * mA;
            float mB = (psum[rB] + psum[64 + rB] + psum[128 + rB] + psum[192 + rB]) * (1.f / 128.f);
            float vB = (psq [rB] + psq [64 + rB] + psq [128 + rB] + psq [192 + rB]) * (1.f / 128.f) - mB * mB;
            float rsA = rsqrtf(vA + EPSV), rsB = rsqrtf(vB + EPSV);
            #pragma unroll
            for (int ni = 0; ni < 4; ni++) {
                int cb = wn * 32 + ni * 8 + tig * 2;
                float gg0 = g2[cb], gg1 = g2[cb + 1];
                float bb0 = b2[cb], bb1 = b2[cb + 1];
                *(__half2*)(Vb + rA * VSTR + cb) = __floats2half2_rn(
                    fmaf((yacc[mi][ni][0] - mA) * rsA, gg0, bb0),
                    fmaf((yacc[mi][ni][1] - mA) * rsA, gg1, bb1));
                *(__half2*)(Vb + rB * VSTR + cb) = __floats2half2_rn(
                    fmaf((yacc[mi][ni][2] - mB) * rsB, gg0, bb0),
                    fmaf((yacc[mi][ni][3] - mB) * rsB, gg1, bb1));
            }
        }
        // yacc dead (y lives in global)

        // ---- MLP: 4 hidden tiles; W1 in BwB, W2 in BwA; 2 barriers/iter ---
        float uacc[2][4][4];
        ZERO_ACC(uacc);
        #pragma unroll 1
        for (int cc = 0; cc < 4; cc++) {
            cp_wait<0>();            // W1(cc) in BwB done
            __syncthreads();         // lny published; prev uacc gemm done (BwA free)
            issueB128(BwA, g_W2T + cc * 128, HIDN, tid); cp_commit();
            float tacc[2][4][4];
            ZERO_ACC(tacc);
            mma_gemm128(Vb, BwB, tacc, wm, wn, lane);

            // gelu -> Gb (per-warp-owned regions; no sync needed before)
            #pragma unroll
            for (int mi = 0; mi < 2; mi++)
                #pragma unroll
                for (int ni = 0; ni < 4; ni++) {
                    int r0 = wm * 32 + mi * 16 + gid;
                    int cb = wn * 32 + ni * 8 + tig * 2;
                    float bb0 = bm1[cc * 128 + cb], bb1 = bm1[cc * 128 + cb + 1];
                    *(__half2*)(Gb + r0 * VSTR + cb) = __floats2half2_rn(
                        gelu_f(tacc[mi][ni][0] + bb0),
                        gelu_f(tacc[mi][ni][1] + bb1));
                    *(__half2*)(Gb + (r0 + 8) * VSTR + cb) = __floats2half2_rn(
                        gelu_f(tacc[mi][ni][2] + bb0),
                        gelu_f(tacc[mi][ni][3] + bb1));
                }
            cp_wait<0>();            // W2(cc) in BwA done
            __syncthreads();         // Gb published; all past tacc (BwB free)
            if (cc < 3) {
                issueB128(BwB, g_W1T + (cc + 1) * 128 * DD, DD, tid);
                cp_commit();
            }
            mma_gemm128(Gb, BwA, uacc, wm, wn, lane);
        }

        // -------- z = y(reload, own addresses) + u + bm2 -> out -----------
        #pragma unroll
        for (int mi = 0; mi < 2; mi++)
            #pragma unroll
            for (int ni = 0; ni < 4; ni++) {
                int r0 = wm * 32 + mi * 16 + gid;
                int cb = wn * 32 + ni * 8 + tig * 2;
                float bb0 = bm2[cb], bb1 = bm2[cb + 1];
                float2 ya = *(float2*)(out + (tile0 + r0) * DD + cb);
                float2 yb = *(float2*)(out + (tile0 + r0 + 8) * DD + cb);
                float2 z0, z1;
                z0.x = ya.x + uacc[mi][ni][0] + bb0;
                z0.y = ya.y + uacc[mi][ni][1] + bb1;
                z1.x = yb.x + uacc[mi][ni][2] + bb0;
                z1.y = yb.y + uacc[mi][ni][3] + bb1;
                *(float2*)(out + (tile0 + r0) * DD + cb)     = z0;
                *(float2*)(out + (tile0 + r0 + 8) * DD + cb) = z1;
            }
    }
}

// ------------------------------ launcher ----------------------------------
extern "C" void kernel_launch(void* const* d_in, const int* in_sizes, int n_in,
                              void* d_out, int out_size)
{
    const float* x   = (const float*)d_in[0];
    const float* g1  = (const float*)d_in[1];
    const float* b1  = (const float*)d_in[2];
    // d_in[3]=Wq, d_in[4]=bq, d_in[7]=rpb : dead
    const float* Wkv = (const float*)d_in[5];
    const float* bkv = (const float*)d_in[6];
    const float* Wp  = (const float*)d_in[8];
    const float* bp  = (const float*)d_in[9];
    const float* g2  = (const float*)d_in[10];
    const float* b2  = (const float*)d_in[11];
    const float* W1  = (const float*)d_in[12];
    const float* bm1 = (const float*)d_in[13];
    const float* W2  = (const float*)d_in[14];
    const float* bm2 = (const float*)d_in[15];
    float* out = (float*)d_out;

    cudaFuncSetAttribute(fused_mma,
                         cudaFuncAttributeMaxDynamicSharedMemorySize,
                         SMEM_BYTES);

    prep_merged<<<321, dim3(32, 8)>>>(W1, W2, Wkv, Wp, bkv, bp);

    const int tokens = in_sizes[0] / CC;   // 65536
    const int ntiles = tokens / MT;        // 1024
    fused_mma<<<PGRID, NTHR, SMEM_BYTES>>>(
        x, g1, b1, g2, b2, bm1, bm2, out, ntiles);
}